// round 1
// baseline (speedup 1.0000x reference)
#include <cuda_runtime.h>
#include <cstdint>

#define BI 32
#define HH 512
#define WW 512
#define HW (HH*WW)

// Bitmask scratch: bit c of word i of row r = pixel (r, i*64+c)
__device__ unsigned long long g_strong[BI][HH][8];
__device__ unsigned long long g_weak[BI][HH][8];

// u8 = floor(clip((x+1)*0.5*256, 0, 255)) — *0.5 and *256 are exact, single rounding at the add
__device__ __forceinline__ float pix_u8(float v){
    float t = __fmul_rn(__fmul_rn(__fadd_rn(v, 1.0f), 0.5f), 256.0f);
    t = fminf(fmaxf(t, 0.0f), 255.0f);
    return floorf(t);
}

// gray = round(0.299r + 0.587g + 0.114b), no FMA contraction, left-assoc, round-half-even
__device__ __forceinline__ float grayv(float r, float g, float b){
    return rintf(__fadd_rn(__fadd_rn(__fmul_rn(0.299f, r), __fmul_rn(0.587f, g)),
                           __fmul_rn(0.114f, b)));
}

#define TW 64
#define TH 32
#define GW (TW+4)   // 68
#define GH (TH+4)   // 36
#define MW (TW+2)   // 66
#define MH (TH+2)   // 34

__global__ __launch_bounds__(256) void canny_stage1(const float* __restrict__ x){
    __shared__ float gs[GH][GW];   // gray, replicate-clamped halo 2
    __shared__ float ms[MH][MW];   // |gx|+|gy|, zero outside image, halo 1

    int b    = blockIdx.z;
    int col0 = blockIdx.x * TW;
    int row0 = blockIdx.y * TH;
    int tid  = threadIdx.y * 64 + threadIdx.x;

    const float* xr = x + (size_t)b * 3 * HW;
    const float* xg = xr + HW;
    const float* xb = xg + HW;

    // Phase 1: gray tile with halo-2 (replicate border, matching pad mode 'edge')
    for (int idx = tid; idx < GH*GW; idx += 256){
        int j = idx / GW, i = idx % GW;
        int r = row0 - 2 + j; r = min(max(r, 0), HH-1);
        int c = col0 - 2 + i; c = min(max(c, 0), WW-1);
        int off = r*WW + c;
        gs[j][i] = grayv(pix_u8(xr[off]), pix_u8(xg[off]), pix_u8(xb[off]));
    }
    __syncthreads();

    // Phase 2: L1 gradient magnitude with halo-1 (zero outside image, matching zero-pad mp)
    for (int idx = tid; idx < MH*MW; idx += 256){
        int j = idx / MW, i = idx % MW;
        int r = row0 - 1 + j, c = col0 - 1 + i;
        float m = 0.0f;
        if (r >= 0 && r < HH && c >= 0 && c < WW){
            int jj = j + 1, ii = i + 1;  // into gs
            float g00 = gs[jj-1][ii-1], g01 = gs[jj-1][ii], g02 = gs[jj-1][ii+1];
            float g10 = gs[jj  ][ii-1],                     g12 = gs[jj  ][ii+1];
            float g20 = gs[jj+1][ii-1], g21 = gs[jj+1][ii], g22 = gs[jj+1][ii+1];
            float gx = (g02 + 2.0f*g12 + g22) - (g00 + 2.0f*g10 + g20);
            float gy = (g20 + 2.0f*g21 + g22) - (g00 + 2.0f*g01 + g02);
            m = fabsf(gx) + fabsf(gy);   // exact integer in f32
        }
        ms[j][i] = m;
    }
    __syncthreads();

    // Phase 3: NMS + thresholds -> bitmasks (warp lanes are 32 consecutive columns)
    int xt   = threadIdx.x;       // 0..63
    int lane = xt & 31;
    int wsel = xt >> 5;
    for (int k = 0; k < 8; ++k){
        int ty = threadIdx.y + 4*k;   // 0..31, same across each warp
        int jj = ty + 2, ii = xt + 2;
        float g00 = gs[jj-1][ii-1], g01 = gs[jj-1][ii], g02 = gs[jj-1][ii+1];
        float g10 = gs[jj  ][ii-1],                     g12 = gs[jj  ][ii+1];
        float g20 = gs[jj+1][ii-1], g21 = gs[jj+1][ii], g22 = gs[jj+1][ii+1];
        float gx = (g02 + 2.0f*g12 + g22) - (g00 + 2.0f*g10 + g20);
        float gy = (g20 + 2.0f*g21 + g22) - (g00 + 2.0f*g01 + g02);
        float ax = fabsf(gx), ay = fabsf(gy);
        float m  = ms[ty+1][xt+1];

        // Exact direction binning (equivalent to degrees(atan2) bins; ties impossible
        // for integer gx,gy vs irrational tan boundaries). gx==gy==0 -> m==0 -> bin irrelevant.
        int dy1, dx1, dy2, dx2;
        if ((double)ay < 0.41421356237309503 * (double)ax){          // b0: horizontal
            dy1 = 0; dx1 = 1;  dy2 = 0;  dx2 = -1;
        } else if ((double)ay > 2.414213562373095 * (double)ax){     // b2: vertical
            dy1 = 1; dx1 = 0;  dy2 = -1; dx2 = 0;
        } else if (gx * gy > 0.0f){                                  // b1
            dy1 = 1; dx1 = 1;  dy2 = -1; dx2 = -1;
        } else {                                                     // b3
            dy1 = -1; dx1 = 1; dy2 = 1;  dx2 = -1;
        }
        float q1 = ms[ty+1+dy1][xt+1+dx1];
        float q2 = ms[ty+1+dy2][xt+1+dx2];
        float nmsv = (m >= q1 && m >= q2) ? m : 0.0f;

        unsigned sbits = __ballot_sync(0xffffffffu, nmsv > 85.0f);
        unsigned wbits = __ballot_sync(0xffffffffu, nmsv > 40.0f);
        if (lane == 0){
            int grow = row0 + ty;
            int word = (col0 >> 5) + wsel;
            ((unsigned*)g_strong)[((size_t)b*HH + grow)*16 + word] = sbits;
            ((unsigned*)g_weak  )[((size_t)b*HH + grow)*16 + word] = wbits;
        }
    }
}

// One CTA per image, one thread per row, row state = 8x u64 in registers.
// s_{k+1} = weak & dilate3x3(s_k); monotone, so early exit on convergence is exact.
__global__ __launch_bounds__(512) void canny_hyst(float* __restrict__ out){
    __shared__ unsigned long long hb[16][2][8];   // per-warp boundary rows (h of lane0 / lane31)
    __shared__ unsigned long long sb2[512][8];    // final bits for coalesced output

    int b    = blockIdx.x;
    int r    = threadIdx.x;
    int lane = r & 31;
    int warp = r >> 5;

    unsigned long long w[8], s[8];
    #pragma unroll
    for (int i = 0; i < 8; i++){ w[i] = g_weak[b][r][i]; s[i] = g_strong[b][r][i]; }

    for (int it = 0; it < 100; ++it){
        unsigned long long h[8];
        #pragma unroll
        for (int i = 0; i < 8; i++) h[i] = s[i] | (s[i] << 1) | (s[i] >> 1);
        #pragma unroll
        for (int i = 0; i < 7; i++){ h[i+1] |= s[i] >> 63; h[i] |= s[i+1] << 63; }

        unsigned long long up[8], dn[8];
        #pragma unroll
        for (int i = 0; i < 8; i++){
            up[i] = __shfl_up_sync  (0xffffffffu, h[i], 1);
            dn[i] = __shfl_down_sync(0xffffffffu, h[i], 1);
        }
        if (lane == 0){
            #pragma unroll
            for (int i = 0; i < 8; i++) hb[warp][0][i] = h[i];
        }
        if (lane == 31){
            #pragma unroll
            for (int i = 0; i < 8; i++) hb[warp][1][i] = h[i];
        }
        __syncthreads();
        if (lane == 0){
            if (warp > 0){
                #pragma unroll
                for (int i = 0; i < 8; i++) up[i] = hb[warp-1][1][i];
            } else {
                #pragma unroll
                for (int i = 0; i < 8; i++) up[i] = 0ull;   // row -1 outside: dilation sees false
            }
        }
        if (lane == 31){
            if (warp < 15){
                #pragma unroll
                for (int i = 0; i < 8; i++) dn[i] = hb[warp+1][0][i];
            } else {
                #pragma unroll
                for (int i = 0; i < 8; i++) dn[i] = 0ull;   // row 512 outside
            }
        }

        unsigned long long ch = 0ull;
        #pragma unroll
        for (int i = 0; i < 8; i++){
            unsigned long long ns = (h[i] | up[i] | dn[i]) & w[i];
            ch |= ns ^ s[i];
            s[i] = ns;
        }
        // barrier also orders this iter's smem reads vs next iter's writes
        if (!__syncthreads_or(ch != 0ull)) break;
    }

    #pragma unroll
    for (int i = 0; i < 8; i++) sb2[r][i] = s[i];
    __syncthreads();

    float* o = out + (size_t)b * HW;
    for (int j = threadIdx.x; j < HW/4; j += 512){
        int pix = j << 2;
        unsigned long long wv = sb2[pix >> 9][(pix >> 6) & 7];
        int sh = pix & 63;
        float4 v;
        v.x = ((wv >> (sh    )) & 1ull) ? 255.0f : 0.0f;
        v.y = ((wv >> (sh + 1)) & 1ull) ? 255.0f : 0.0f;
        v.z = ((wv >> (sh + 2)) & 1ull) ? 255.0f : 0.0f;
        v.w = ((wv >> (sh + 3)) & 1ull) ? 255.0f : 0.0f;
        ((float4*)o)[j] = v;
    }
}

extern "C" void kernel_launch(void* const* d_in, const int* in_sizes, int n_in,
                              void* d_out, int out_size){
    const float* x = (const float*)d_in[0];
    dim3 g1(WW/TW, HH/TH, BI), b1(64, 4, 1);
    canny_stage1<<<g1, b1>>>(x);
    canny_hyst<<<BI, 512>>>((float*)d_out);
}

// round 2
// speedup vs baseline: 1.5715x; 1.5715x over previous
#include <cuda_runtime.h>
#include <cstdint>

#define BI 32
#define HH 512
#define WW 512
#define HW (HH*WW)

// Bitmask scratch: bit c of word i of row r = pixel (r, i*64+c)
__device__ unsigned long long g_strong[BI][HH][8];
__device__ unsigned long long g_weak[BI][HH][8];

// u8 = floor(clip((x+1)*0.5*256, 0, 255)) — *0.5 and *256 are exact, single rounding at the add
__device__ __forceinline__ float pix_u8(float v){
    float t = __fmul_rn(__fmul_rn(__fadd_rn(v, 1.0f), 0.5f), 256.0f);
    t = fminf(fmaxf(t, 0.0f), 255.0f);
    return floorf(t);
}

// gray = round(0.299r + 0.587g + 0.114b), no FMA contraction, left-assoc, round-half-even
__device__ __forceinline__ float grayv(float r, float g, float b){
    return rintf(__fadd_rn(__fadd_rn(__fmul_rn(0.299f, r), __fmul_rn(0.587f, g)),
                           __fmul_rn(0.114f, b)));
}

#define TW 64
#define TH 32
#define GW (TW+4)   // 68
#define GH (TH+4)   // 36
#define MW (TW+2)   // 66
#define MH (TH+2)   // 34

__global__ __launch_bounds__(256) void canny_stage1(const float* __restrict__ x){
    __shared__ float gs[GH][GW];   // gray, replicate-clamped halo 2
    __shared__ float ms[MH][MW];   // |gx|+|gy|, zero outside image, halo 1

    int b    = blockIdx.z;
    int col0 = blockIdx.x * TW;
    int row0 = blockIdx.y * TH;
    int tid  = threadIdx.y * 64 + threadIdx.x;

    const float* xr = x + (size_t)b * 3 * HW;
    const float* xg = xr + HW;
    const float* xb = xg + HW;

    // Phase 1: gray tile with halo-2 (replicate border, matching pad mode 'edge')
    for (int idx = tid; idx < GH*GW; idx += 256){
        int j = idx / GW, i = idx % GW;
        int r = row0 - 2 + j; r = min(max(r, 0), HH-1);
        int c = col0 - 2 + i; c = min(max(c, 0), WW-1);
        int off = r*WW + c;
        gs[j][i] = grayv(pix_u8(xr[off]), pix_u8(xg[off]), pix_u8(xb[off]));
    }
    __syncthreads();

    // Phase 2: L1 gradient magnitude with halo-1 (zero outside image, matching zero-pad mp)
    for (int idx = tid; idx < MH*MW; idx += 256){
        int j = idx / MW, i = idx % MW;
        int r = row0 - 1 + j, c = col0 - 1 + i;
        float m = 0.0f;
        if (r >= 0 && r < HH && c >= 0 && c < WW){
            int jj = j + 1, ii = i + 1;  // into gs
            float g00 = gs[jj-1][ii-1], g01 = gs[jj-1][ii], g02 = gs[jj-1][ii+1];
            float g10 = gs[jj  ][ii-1],                     g12 = gs[jj  ][ii+1];
            float g20 = gs[jj+1][ii-1], g21 = gs[jj+1][ii], g22 = gs[jj+1][ii+1];
            float gx = (g02 + 2.0f*g12 + g22) - (g00 + 2.0f*g10 + g20);
            float gy = (g20 + 2.0f*g21 + g22) - (g00 + 2.0f*g01 + g02);
            m = fabsf(gx) + fabsf(gy);   // exact integer in f32
        }
        ms[j][i] = m;
    }
    __syncthreads();

    // Phase 3: NMS + thresholds -> bitmasks (warp lanes are 32 consecutive columns)
    int xt   = threadIdx.x;       // 0..63
    int lane = xt & 31;
    int wsel = xt >> 5;
    for (int k = 0; k < 8; ++k){
        int ty = threadIdx.y + 4*k;   // 0..31, same across each warp
        int jj = ty + 2, ii = xt + 2;
        float g00 = gs[jj-1][ii-1], g01 = gs[jj-1][ii], g02 = gs[jj-1][ii+1];
        float g10 = gs[jj  ][ii-1],                     g12 = gs[jj  ][ii+1];
        float g20 = gs[jj+1][ii-1], g21 = gs[jj+1][ii], g22 = gs[jj+1][ii+1];
        float gx = (g02 + 2.0f*g12 + g22) - (g00 + 2.0f*g10 + g20);
        float gy = (g20 + 2.0f*g21 + g22) - (g00 + 2.0f*g01 + g02);
        float m  = ms[ty+1][xt+1];

        // Exact integer direction binning (no FP64).
        // gx, gy are exact integers in f32, |g| <= 1020.
        //   b0: ay < (sqrt2-1)*ax  <=>  (ay+ax)^2 < 2*ax^2
        //   b2: ay > (sqrt2+1)*ax  <=>  (ay>ax) && (ay-ax)^2 > 2*ax^2
        // Ties with the irrational boundary are impossible for integers (ax>0),
        // and ax==0 cases resolve correctly (see derivation).
        int igx = (int)gx, igy = (int)gy;
        int ax = abs(igx), ay = abs(igy);
        int sum = ax + ay, dif = ay - ax;
        int ax2x2 = 2 * ax * ax;

        int dy1, dx1, dy2, dx2;
        if (sum * sum < ax2x2){                       // b0: horizontal
            dy1 = 0; dx1 = 1;  dy2 = 0;  dx2 = -1;
        } else if (dif > 0 && dif * dif > ax2x2){     // b2: vertical
            dy1 = 1; dx1 = 0;  dy2 = -1; dx2 = 0;
        } else if (igx * igy > 0){                    // b1
            dy1 = 1; dx1 = 1;  dy2 = -1; dx2 = -1;
        } else {                                      // b3
            dy1 = -1; dx1 = 1; dy2 = 1;  dx2 = -1;
        }
        float q1 = ms[ty+1+dy1][xt+1+dx1];
        float q2 = ms[ty+1+dy2][xt+1+dx2];
        float nmsv = (m >= q1 && m >= q2) ? m : 0.0f;

        unsigned sbits = __ballot_sync(0xffffffffu, nmsv > 85.0f);
        unsigned wbits = __ballot_sync(0xffffffffu, nmsv > 40.0f);
        if (lane == 0){
            int grow = row0 + ty;
            int word = (col0 >> 5) + wsel;
            ((unsigned*)g_strong)[((size_t)b*HH + grow)*16 + word] = sbits;
            ((unsigned*)g_weak  )[((size_t)b*HH + grow)*16 + word] = wbits;
        }
    }
}

// One CTA per image, one thread per row, row state = 8x u64 in registers.
// s_{k+1} = weak & dilate3x3(s_k); monotone, so early exit on convergence is exact.
__global__ __launch_bounds__(512) void canny_hyst(float* __restrict__ out){
    __shared__ unsigned long long hb[16][2][8];   // per-warp boundary rows (h of lane0 / lane31)
    __shared__ unsigned long long sb2[512][8];    // final bits for coalesced output

    int b    = blockIdx.x;
    int r    = threadIdx.x;
    int lane = r & 31;
    int warp = r >> 5;

    unsigned long long w[8], s[8];
    #pragma unroll
    for (int i = 0; i < 8; i++){ w[i] = g_weak[b][r][i]; s[i] = g_strong[b][r][i]; }

    for (int it = 0; it < 100; ++it){
        unsigned long long h[8];
        #pragma unroll
        for (int i = 0; i < 8; i++) h[i] = s[i] | (s[i] << 1) | (s[i] >> 1);
        #pragma unroll
        for (int i = 0; i < 7; i++){ h[i+1] |= s[i] >> 63; h[i] |= s[i+1] << 63; }

        unsigned long long up[8], dn[8];
        #pragma unroll
        for (int i = 0; i < 8; i++){
            up[i] = __shfl_up_sync  (0xffffffffu, h[i], 1);
            dn[i] = __shfl_down_sync(0xffffffffu, h[i], 1);
        }
        if (lane == 0){
            #pragma unroll
            for (int i = 0; i < 8; i++) hb[warp][0][i] = h[i];
        }
        if (lane == 31){
            #pragma unroll
            for (int i = 0; i < 8; i++) hb[warp][1][i] = h[i];
        }
        __syncthreads();
        if (lane == 0){
            if (warp > 0){
                #pragma unroll
                for (int i = 0; i < 8; i++) up[i] = hb[warp-1][1][i];
            } else {
                #pragma unroll
                for (int i = 0; i < 8; i++) up[i] = 0ull;   // row -1 outside: dilation sees false
            }
        }
        if (lane == 31){
            if (warp < 15){
                #pragma unroll
                for (int i = 0; i < 8; i++) dn[i] = hb[warp+1][0][i];
            } else {
                #pragma unroll
                for (int i = 0; i < 8; i++) dn[i] = 0ull;   // row 512 outside
            }
        }

        unsigned long long ch = 0ull;
        #pragma unroll
        for (int i = 0; i < 8; i++){
            unsigned long long ns = (h[i] | up[i] | dn[i]) & w[i];
            ch |= ns ^ s[i];
            s[i] = ns;
        }
        // barrier also orders this iter's smem reads vs next iter's writes
        if (!__syncthreads_or(ch != 0ull)) break;
    }

    #pragma unroll
    for (int i = 0; i < 8; i++) sb2[r][i] = s[i];
    __syncthreads();

    float* o = out + (size_t)b * HW;
    for (int j = threadIdx.x; j < HW/4; j += 512){
        int pix = j << 2;
        unsigned long long wv = sb2[pix >> 9][(pix >> 6) & 7];
        int sh = pix & 63;
        float4 v;
        v.x = ((wv >> (sh    )) & 1ull) ? 255.0f : 0.0f;
        v.y = ((wv >> (sh + 1)) & 1ull) ? 255.0f : 0.0f;
        v.z = ((wv >> (sh + 2)) & 1ull) ? 255.0f : 0.0f;
        v.w = ((wv >> (sh + 3)) & 1ull) ? 255.0f : 0.0f;
        ((float4*)o)[j] = v;
    }
}

extern "C" void kernel_launch(void* const* d_in, const int* in_sizes, int n_in,
                              void* d_out, int out_size){
    const float* x = (const float*)d_in[0];
    dim3 g1(WW/TW, HH/TH, BI), b1(64, 4, 1);
    canny_stage1<<<g1, b1>>>(x);
    canny_hyst<<<BI, 512>>>((float*)d_out);
}